// round 1
// baseline (speedup 1.0000x reference)
#include <cuda_runtime.h>
#include <math.h>

typedef unsigned long long ull;

constexpr int Bb = 8, Ll = 2048, Hh = 256;
constexpr int IT = 64, JT = 64;

// scratch (device globals: allocation-free)
__device__ float g_st[Bb * Ll];
__device__ float g_so[Bb * Ll];
__device__ float g_mult[Bb * Ll];
__device__ float g_base[Ll];

// ---------------- packed f32x2 helpers (Blackwell FFMA2 path) ----------------
__device__ __forceinline__ ull pack2(float x) {
    unsigned int u = __float_as_uint(x);
    ull r;
    asm("mov.b64 %0, {%1, %1};" : "=l"(r) : "r"(u));
    return r;
}
__device__ __forceinline__ void ffma2(ull& d, ull a, ull b) {
    asm("fma.rn.f32x2 %0, %1, %2, %0;" : "+l"(d) : "l"(a), "l"(b));
}
__device__ __forceinline__ void mul2(ull& d, ull b) {
    asm("mul.rn.f32x2 %0, %0, %1;" : "+l"(d) : "l"(b));
}
__device__ __forceinline__ float2 unpk(ull v) {
    unsigned int lo, hi;
    asm("mov.b64 {%0, %1}, %2;" : "=r"(lo), "=r"(hi) : "l"(v));
    return make_float2(__uint_as_float(lo), __uint_as_float(hi));
}

// ---------------- prep: opinion-tag multiplier + position-bias table --------
__global__ void prep_kernel(const int* __restrict__ pos) {
    int idx = blockIdx.x * blockDim.x + threadIdx.x;
    if (idx < Bb * Ll) {
        int p = pos[idx];
        bool op = (p >= 19 && p <= 21) || (p >= 33 && p <= 35) || (p >= 41 && p <= 46);
        g_mult[idx] = op ? 8.0f : 1.0f;
    }
    if (idx < Ll) {
        g_base[idx] = (idx == 0) ? 0.5f : (1.0f / log2f(2.0f + (float)idx));
    }
}

// ---------------- stage 1: s[m] = sum_h tanh(X[m]·W[h] + b[h]) * wa_half[h] --
// grid: 512 blocks of 256 threads, 32 tokens per block.
__global__ __launch_bounds__(256) void s1_kernel(
    const float* __restrict__ X, const float* __restrict__ W,
    const float* __restrict__ bias, const float* __restrict__ wah, int sel)
{
    __shared__ float Xs[32][34];       // [k][m], transposed
    __shared__ float Ws[32 * 256];     // [k][h], transposed

    const int tid = threadIdx.x;
    const int m0 = blockIdx.x * 32;
    const int hg = tid & 15;           // 16 h-groups: h = hg*4 + q*64 + c
    const int mg = tid >> 4;           // 16 m-groups of 2 rows

    ull acc[2][8] = {};

    for (int k0 = 0; k0 < Hh; k0 += 32) {
        __syncthreads();
        // load X tile (32 tokens x 32 k) transposed
        {
            int m = tid >> 3;
            int kq = (tid & 7) * 4;
            float4 x4 = *(const float4*)(X + (size_t)(m0 + m) * Hh + k0 + kq);
            Xs[kq + 0][m] = x4.x; Xs[kq + 1][m] = x4.y;
            Xs[kq + 2][m] = x4.z; Xs[kq + 3][m] = x4.w;
        }
        // load W tile (256 h x 32 k) transposed to [k][h]
        #pragma unroll
        for (int p = 0; p < 8; ++p) {
            int h = p * 32 + (tid >> 3);
            int kq = (tid & 7) * 4;
            float4 w4 = *(const float4*)(W + (size_t)h * Hh + k0 + kq);
            Ws[(kq + 0) * 256 + h] = w4.x; Ws[(kq + 1) * 256 + h] = w4.y;
            Ws[(kq + 2) * 256 + h] = w4.z; Ws[(kq + 3) * 256 + h] = w4.w;
        }
        __syncthreads();
        #pragma unroll
        for (int k = 0; k < 32; ++k) {
            float2 xm = *(const float2*)&Xs[k][mg * 2];
            ull x0 = pack2(xm.x), x1 = pack2(xm.y);
            const ulonglong2* wr = (const ulonglong2*)(Ws + k * 256);
            ulonglong2 v0 = wr[hg], v1 = wr[hg + 16], v2 = wr[hg + 32], v3 = wr[hg + 48];
            ffma2(acc[0][0], x0, v0.x); ffma2(acc[0][1], x0, v0.y);
            ffma2(acc[0][2], x0, v1.x); ffma2(acc[0][3], x0, v1.y);
            ffma2(acc[0][4], x0, v2.x); ffma2(acc[0][5], x0, v2.y);
            ffma2(acc[0][6], x0, v3.x); ffma2(acc[0][7], x0, v3.y);
            ffma2(acc[1][0], x1, v0.x); ffma2(acc[1][1], x1, v0.y);
            ffma2(acc[1][2], x1, v1.x); ffma2(acc[1][3], x1, v1.y);
            ffma2(acc[1][4], x1, v2.x); ffma2(acc[1][5], x1, v2.y);
            ffma2(acc[1][6], x1, v3.x); ffma2(acc[1][7], x1, v3.y);
        }
    }

    // epilogue: tanh + dot with wa_half, reduce across 16 h-group lanes
    float part0 = 0.f, part1 = 0.f;
    #pragma unroll
    for (int q = 0; q < 4; ++q) {
        int h0 = q * 64 + hg * 4;
        float4 b4 = bias ? *(const float4*)(bias + h0) : make_float4(0.f, 0.f, 0.f, 0.f);
        float4 w4 = *(const float4*)(wah + h0);
        float2 a0 = unpk(acc[0][2 * q]);
        float2 a1 = unpk(acc[0][2 * q + 1]);
        part0 += tanhf(a0.x + b4.x) * w4.x + tanhf(a0.y + b4.y) * w4.y
               + tanhf(a1.x + b4.z) * w4.z + tanhf(a1.y + b4.w) * w4.w;
        float2 c0 = unpk(acc[1][2 * q]);
        float2 c1 = unpk(acc[1][2 * q + 1]);
        part1 += tanhf(c0.x + b4.x) * w4.x + tanhf(c0.y + b4.y) * w4.y
               + tanhf(c1.x + b4.z) * w4.z + tanhf(c1.y + b4.w) * w4.w;
    }
    #pragma unroll
    for (int off = 8; off > 0; off >>= 1) {
        part0 += __shfl_down_sync(0xffffffffu, part0, off, 16);
        part1 += __shfl_down_sync(0xffffffffu, part1, off, 16);
    }
    if (hg == 0) {
        float* outS = sel ? g_so : g_st;
        outS[m0 + mg * 2 + 0] = part0;
        outS[m0 + mg * 2 + 1] = part1;
    }
}

// ---------------- stage 2: fused biased softmax + att@V ---------------------
// grid: (L/IT, B) = (32, 8); 256 threads; dynamic smem ~92.7 KB; 2 blocks/SM.
constexpr int SMEM2_FLOATS = JT * Hh          // Vs        16384
                           + JT * 68          // wT        4352
                           + Ll               // base      2048
                           + 6 * IT;          // st/so/mult/m/l/fac
constexpr int SMEM2_BYTES = SMEM2_FLOATS * 4;

__global__ __launch_bounds__(256, 2) void attn_kernel(
    const float* __restrict__ opinion, const float* __restrict__ ba,
    float* __restrict__ out)
{
    extern __shared__ float sm[];
    float* sVs   = sm;                       // [JT][256]
    float* sWt   = sVs + JT * Hh;            // [JT][68]  exp-weights, transposed
    float* sBase = sWt + JT * 68;            // [2048]
    float* st_s  = sBase + Ll;               // [64]
    float* soB_s = st_s + IT;
    float* mult_s = soB_s + IT;
    float* sm_m  = mult_s + IT;
    float* sm_l  = sm_m + IT;
    float* sm_fac = sm_l + IT;

    const int tid = threadIdx.x;
    const int b = blockIdx.y;
    const int i0 = blockIdx.x * IT;
    const int hg = tid & 15;      // 16 h-chunks of 4, strided by 64
    const int ig = tid >> 4;      // 16 i-groups of 4 rows
    const int wi = tid >> 2;      // weight-phase row
    const int ws = tid & 3;       // weight-phase column-quarter
    const float* V = opinion + (size_t)b * Ll * Hh;

    for (int q = tid; q < Ll; q += 256) sBase[q] = g_base[q];
    if (tid < IT) {
        st_s[tid] = g_st[b * Ll + i0 + tid] + ba[0];
        sm_m[tid] = -INFINITY;
        sm_l[tid] = 0.0f;
    }

    ull acc[4][8] = {};

    for (int jt = 0; jt < Ll / JT; ++jt) {
        const int j0 = jt * JT;
        __syncthreads();   // prior main loop done reading Vs/wT (and init visible)
        // load V tile (contiguous 64x256 floats) + per-j vectors
        {
            const float4* src = (const float4*)(V + (size_t)j0 * Hh);
            float4* dst = (float4*)sVs;
            #pragma unroll
            for (int q = 0; q < (JT * Hh / 4) / 256; ++q)
                dst[q * 256 + tid] = src[q * 256 + tid];
            if (tid < JT) {
                soB_s[tid]  = g_so[b * Ll + j0 + tid];
                mult_s[tid] = g_mult[b * Ll + j0 + tid];
            }
        }
        __syncthreads();
        // weight pass 1: raw scores + tile max (4 threads per row, 16 j each)
        float sti = st_s[wi];
        int gi = i0 + wi;
        float mx = -INFINITY;
        #pragma unroll
        for (int t = 0; t < 16; ++t) {
            int jj = ws * 16 + t;
            int d = gi - (j0 + jj); d = d < 0 ? -d : d;
            float sc = (sti + soB_s[jj]) * (mult_s[jj] * sBase[d]);
            sWt[jj * 68 + wi] = sc;
            mx = fmaxf(mx, sc);
        }
        mx = fmaxf(mx, __shfl_xor_sync(0xffffffffu, mx, 1));
        mx = fmaxf(mx, __shfl_xor_sync(0xffffffffu, mx, 2));
        float mo = sm_m[wi];
        float mn = fmaxf(mo, mx);
        // weight pass 2: exponentiate + partial sums
        float es = 0.f;
        #pragma unroll
        for (int t = 0; t < 16; ++t) {
            int jj = ws * 16 + t;
            float e = __expf(sWt[jj * 68 + wi] - mn);
            sWt[jj * 68 + wi] = e;
            es += e;
        }
        es += __shfl_xor_sync(0xffffffffu, es, 1);
        es += __shfl_xor_sync(0xffffffffu, es, 2);
        if (ws == 0) {
            float f = __expf(mo - mn);
            sm_fac[wi] = f;
            sm_m[wi] = mn;
            sm_l[wi] = sm_l[wi] * f + es;
        }
        __syncthreads();   // wT + fac visible
        // rescale accumulators by exp(m_old - m_new)
        #pragma unroll
        for (int r = 0; r < 4; ++r) {
            ull f2 = pack2(sm_fac[ig * 4 + r]);
            #pragma unroll
            for (int u = 0; u < 8; ++u) mul2(acc[r][u], f2);
        }
        // main rank-JT update: acc[i][h] += w[i][j] * V[j][h]  (FFMA2 packed)
        #pragma unroll 4
        for (int jj = 0; jj < JT; ++jj) {
            const ulonglong2* vr = (const ulonglong2*)(sVs + jj * Hh);
            ulonglong2 v0 = vr[hg], v1 = vr[hg + 16], v2 = vr[hg + 32], v3 = vr[hg + 48];
            float4 wf = *(const float4*)(sWt + jj * 68 + ig * 4);
            ull w0 = pack2(wf.x), w1 = pack2(wf.y), w2 = pack2(wf.z), w3 = pack2(wf.w);
            ffma2(acc[0][0], w0, v0.x); ffma2(acc[0][1], w0, v0.y);
            ffma2(acc[0][2], w0, v1.x); ffma2(acc[0][3], w0, v1.y);
            ffma2(acc[0][4], w0, v2.x); ffma2(acc[0][5], w0, v2.y);
            ffma2(acc[0][6], w0, v3.x); ffma2(acc[0][7], w0, v3.y);
            ffma2(acc[1][0], w1, v0.x); ffma2(acc[1][1], w1, v0.y);
            ffma2(acc[1][2], w1, v1.x); ffma2(acc[1][3], w1, v1.y);
            ffma2(acc[1][4], w1, v2.x); ffma2(acc[1][5], w1, v2.y);
            ffma2(acc[1][6], w1, v3.x); ffma2(acc[1][7], w1, v3.y);
            ffma2(acc[2][0], w2, v0.x); ffma2(acc[2][1], w2, v0.y);
            ffma2(acc[2][2], w2, v1.x); ffma2(acc[2][3], w2, v1.y);
            ffma2(acc[2][4], w2, v2.x); ffma2(acc[2][5], w2, v2.y);
            ffma2(acc[2][6], w2, v3.x); ffma2(acc[2][7], w2, v3.y);
            ffma2(acc[3][0], w3, v0.x); ffma2(acc[3][1], w3, v0.y);
            ffma2(acc[3][2], w3, v1.x); ffma2(acc[3][3], w3, v1.y);
            ffma2(acc[3][4], w3, v2.x); ffma2(acc[3][5], w3, v2.y);
            ffma2(acc[3][6], w3, v3.x); ffma2(acc[3][7], w3, v3.y);
        }
    }

    __syncthreads();
    // epilogue: divide by softmax denominator, store
    #pragma unroll
    for (int r = 0; r < 4; ++r) {
        int gi = i0 + ig * 4 + r;
        ull iv = pack2(1.0f / sm_l[ig * 4 + r]);
        float* op = out + ((size_t)b * Ll + gi) * Hh;
        #pragma unroll
        for (int q = 0; q < 4; ++q) {
            ull a0 = acc[r][2 * q];     mul2(a0, iv);
            ull a1 = acc[r][2 * q + 1]; mul2(a1, iv);
            ulonglong2 st2; st2.x = a0; st2.y = a1;
            *(ulonglong2*)(op + q * 64 + hg * 4) = st2;
        }
    }
}

// ---------------- launch ----------------------------------------------------
extern "C" void kernel_launch(void* const* d_in, const int* in_sizes, int n_in,
                              void* d_out, int out_size) {
    const float* opinion = (const float*)d_in[0];
    const float* text    = (const float*)d_in[1];
    const int*   pos     = (const int*)d_in[2];
    const float* Wt      = (const float*)d_in[3];
    const float* bt      = (const float*)d_in[4];
    const float* Wo      = (const float*)d_in[5];
    const float* wa      = (const float*)d_in[6];
    const float* ba      = (const float*)d_in[7];
    float* out = (float*)d_out;

    prep_kernel<<<(Bb * Ll + 255) / 256, 256>>>(pos);
    s1_kernel<<<(Bb * Ll) / 32, 256>>>(text, Wt, bt, wa, 0);
    s1_kernel<<<(Bb * Ll) / 32, 256>>>(opinion, Wo, nullptr, wa + Hh, 1);

    cudaFuncSetAttribute((const void*)attn_kernel,
                         cudaFuncAttributeMaxDynamicSharedMemorySize, SMEM2_BYTES);
    dim3 grid2(Ll / IT, Bb);
    attn_kernel<<<grid2, 256, SMEM2_BYTES>>>(opinion, ba, out);
}

// round 4
// speedup vs baseline: 4.1304x; 4.1304x over previous
#include <cuda_runtime.h>
#include <cuda_bf16.h>
#include <math.h>
#include <cstdint>

constexpr int Bb = 8, Ll = 2048, Hh = 256;
constexpr int JT = 64, NC = Ll / JT;   // pass2 j-chunks
constexpr int STRB = 144;              // padded smem row stride (bytes) = 72 bf16

// ---------------- device scratch (allocation-free) ---------------------------
__device__ float  g_st[Bb * Ll];
__device__ float  g_so[Bb * Ll];
__device__ float  g_q [Bb * Ll];                     // mult_j * log2(e)
__device__ float2 g_qs[Bb * Ll];                     // {q_j, q_j * so_j}
__device__ float  g_c [Bb * Ll];                     // -(m_i + log2 l_i)
__device__ float  g_base[Ll];
__device__ __nv_bfloat16 g_vhi[(size_t)Bb * Hh * Ll]; // V^T [B][H][L] hi
__device__ __nv_bfloat16 g_vlo[(size_t)Bb * Hh * Ll]; // lo residual

// ---------------- small helpers ----------------------------------------------
__device__ __forceinline__ uint32_t su32(const void* p) {
    return (uint32_t)__cvta_generic_to_shared(p);
}
__device__ __forceinline__ float ex2f(float x) {
    float r; asm("ex2.approx.f32 %0, %1;" : "=f"(r) : "f"(x)); return r;
}
__device__ __forceinline__ float lg2f(float x) {
    float r; asm("lg2.approx.f32 %0, %1;" : "=f"(r) : "f"(x)); return r;
}
__device__ __forceinline__ void ldm4(uint32_t& r0, uint32_t& r1, uint32_t& r2,
                                     uint32_t& r3, uint32_t a) {
    asm volatile("ldmatrix.sync.aligned.m8n8.x4.shared.b16 {%0,%1,%2,%3}, [%4];"
        : "=r"(r0), "=r"(r1), "=r"(r2), "=r"(r3) : "r"(a));
}
__device__ __forceinline__ void mma16816(float* c, const uint32_t* a,
                                         uint32_t b0, uint32_t b1) {
    asm volatile("mma.sync.aligned.m16n8k16.row.col.f32.bf16.bf16.f32 "
        "{%0,%1,%2,%3}, {%4,%5,%6,%7}, {%8,%9}, {%0,%1,%2,%3};"
        : "+f"(c[0]), "+f"(c[1]), "+f"(c[2]), "+f"(c[3])
        : "r"(a[0]), "r"(a[1]), "r"(a[2]), "r"(a[3]), "r"(b0), "r"(b1));
}
// split (p0,p1) into packed bf16x2 hi + residual lo
__device__ __forceinline__ void split2(float p0, float p1, uint32_t& hi, uint32_t& lo) {
    asm("cvt.rn.bf16x2.f32 %0, %1, %2;" : "=r"(hi) : "f"(p1), "f"(p0));
    float h0 = __uint_as_float(hi << 16);
    float h1 = __uint_as_float(hi & 0xffff0000u);
    float r0 = p0 - h0, r1 = p1 - h1;
    asm("cvt.rn.bf16x2.f32 %0, %1, %2;" : "=r"(lo) : "f"(r1), "f"(r0));
}
__device__ __forceinline__ void cp16(uint32_t dst, const void* src) {
    asm volatile("cp.async.cg.shared.global [%0], [%1], 16;"
        :: "r"(dst), "l"(src) : "memory");
}

// ---------------- prep0: multiplier + base table -----------------------------
__global__ void prep0_kernel(const int* __restrict__ pos) {
    int idx = blockIdx.x * blockDim.x + threadIdx.x;
    if (idx < Bb * Ll) {
        int p = pos[idx];
        bool op = (p >= 19 && p <= 21) || (p >= 33 && p <= 35) || (p >= 41 && p <= 46);
        g_q[idx] = (op ? 8.0f : 1.0f) * 1.44269504088896340736f;
    }
    if (idx < Ll) g_base[idx] = (idx == 0) ? 0.5f : (1.0f / log2f(2.0f + (float)idx));
}

// ---------------- prep2: pack {q, q*so} --------------------------------------
__global__ void prep2_kernel() {
    int idx = blockIdx.x * blockDim.x + threadIdx.x;
    if (idx < Bb * Ll) g_qs[idx] = make_float2(g_q[idx], g_q[idx] * g_so[idx]);
}

// ---------------- prepV: transpose V -> [B][H][L] bf16 hi/lo ----------------
__global__ __launch_bounds__(256) void prepv_kernel(const float* __restrict__ V) {
    __shared__ float tile[32][33];
    const int b = blockIdx.z, h0 = blockIdx.y * 32, j0 = blockIdx.x * 32;
    const int tid = threadIdx.x, c = tid & 31, r0 = tid >> 5;
    #pragma unroll
    for (int k = 0; k < 4; ++k) {
        int r = r0 + k * 8;
        tile[r][c] = V[((size_t)b * Ll + j0 + r) * Hh + h0 + c];
    }
    __syncthreads();
    #pragma unroll
    for (int k = 0; k < 4; ++k) {
        int hh = r0 + k * 8;
        float v = tile[c][hh];
        __nv_bfloat16 hi = __float2bfloat16(v);
        float lo = v - __bfloat162float(hi);
        size_t o = ((size_t)b * Hh + h0 + hh) * Ll + j0 + c;
        g_vhi[o] = hi;
        g_vlo[o] = __float2bfloat16(lo);
    }
}

// ---------------- stage 1: bf16-split MMA GEMM + tanh·wa reduction -----------
// block: 128 m-rows x 256 h, 8 warps (2 m-halves x 4 h-quarters), K=256 in 4 chunks
constexpr int S1_XHI = 0;
constexpr int S1_XLO = 128 * STRB;             // 18432
constexpr int S1_WHI = 2 * 128 * STRB;         // 36864
constexpr int S1_WLO = S1_WHI + 256 * STRB;    // 73728
constexpr int S1_RED = S1_WLO + 256 * STRB;    // 110592: float[4][128]
constexpr int S1_SMEM = S1_RED + 4 * 128 * 4;  // 112640

__global__ __launch_bounds__(256, 1) void s1_mma_kernel(
    const float* __restrict__ X, const float* __restrict__ W,
    const float* __restrict__ bias, const float* __restrict__ wah, int sel)
{
    extern __shared__ char smc[];
    const int tid = threadIdx.x, wid = tid >> 5, lane = tid & 31;
    const int m0 = blockIdx.x * 128;
    const int wi = wid >> 2, wh = wid & 3;

    const uint32_t xhi = su32(smc + S1_XHI), xlo = su32(smc + S1_XLO);
    const uint32_t whi = su32(smc + S1_WHI), wlo = su32(smc + S1_WLO);

    // ldmatrix per-lane offsets (A-frag order / B-frag order)
    const int sub = lane >> 3, lr = lane & 7;
    const uint32_t lrA = (uint32_t)((lr + (sub & 1) * 8) * STRB + (sub >> 1) * 16);
    const uint32_t lrB = (uint32_t)((lr + (sub >> 1) * 8) * STRB + (sub & 1) * 16);

    float C[4][8][4] = {};

    for (int kc = 0; kc < 4; ++kc) {
        __syncthreads();
        // load + split X tile: 128 rows x 64 k
        #pragma unroll
        for (int q = 0; q < 8; ++q) {
            int idx = tid + q * 256;
            int r = idx >> 4, s2 = idx & 15;
            float4 v = *(const float4*)(X + (size_t)(m0 + r) * Hh + kc * 64 + s2 * 4);
            uint32_t h01, l01, h23, l23;
            split2(v.x, v.y, h01, l01);
            split2(v.z, v.w, h23, l23);
            *(uint2*)(smc + S1_XHI + r * STRB + s2 * 8) = make_uint2(h01, h23);
            *(uint2*)(smc + S1_XLO + r * STRB + s2 * 8) = make_uint2(l01, l23);
        }
        // load + split W tile: 256 rows x 64 k
        #pragma unroll
        for (int q = 0; q < 16; ++q) {
            int idx = tid + q * 256;
            int r = idx >> 4, s2 = idx & 15;
            float4 v = *(const float4*)(W + (size_t)r * Hh + kc * 64 + s2 * 4);
            uint32_t h01, l01, h23, l23;
            split2(v.x, v.y, h01, l01);
            split2(v.z, v.w, h23, l23);
            *(uint2*)(smc + S1_WHI + r * STRB + s2 * 8) = make_uint2(h01, h23);
            *(uint2*)(smc + S1_WLO + r * STRB + s2 * 8) = make_uint2(l01, l23);
        }
        __syncthreads();
        #pragma unroll
        for (int kk = 0; kk < 4; ++kk) {
            const uint32_t kb = kk * 32;
            uint32_t bh[4][4], bl[4][4];
            #pragma unroll
            for (int nt = 0; nt < 4; ++nt) {
                uint32_t off = (uint32_t)((wh * 64 + nt * 16) * STRB) + kb + lrB;
                ldm4(bh[nt][0], bh[nt][1], bh[nt][2], bh[nt][3], whi + off);
                ldm4(bl[nt][0], bl[nt][1], bl[nt][2], bl[nt][3], wlo + off);
            }
            #pragma unroll
            for (int mt = 0; mt < 4; ++mt) {
                uint32_t aoff = (uint32_t)((wi * 64 + mt * 16) * STRB) + kb + lrA;
                uint32_t ah[4], al[4];
                ldm4(ah[0], ah[1], ah[2], ah[3], xhi + aoff);
                ldm4(al[0], al[1], al[2], al[3], xlo + aoff);
                #pragma unroll
                for (int nt = 0; nt < 4; ++nt) {
                    mma16816(C[mt][2 * nt],     ah, bh[nt][0], bh[nt][1]);
                    mma16816(C[mt][2 * nt],     al, bh[nt][0], bh[nt][1]);
                    mma16816(C[mt][2 * nt],     ah, bl[nt][0], bl[nt][1]);
                    mma16816(C[mt][2 * nt + 1], ah, bh[nt][2], bh[nt][3]);
                    mma16816(C[mt][2 * nt + 1], al, bh[nt][2], bh[nt][3]);
                    mma16816(C[mt][2 * nt + 1], ah, bl[nt][2], bl[nt][3]);
                }
            }
        }
    }

    // epilogue: st[m] = sum_h tanh(C + bias_h) * wa_h
    float* sred = (float*)(smc + S1_RED);
    const int g = lane >> 2, tig = lane & 3;
    __syncthreads();
    #pragma unroll
    for (int mt = 0; mt < 4; ++mt) {
        float p0 = 0.f, p1 = 0.f;
        #pragma unroll
        for (int nt = 0; nt < 8; ++nt) {
            int h = wh * 64 + nt * 8 + tig * 2;
            float b0 = bias ? __ldg(bias + h)     : 0.f;
            float b1 = bias ? __ldg(bias + h + 1) : 0.f;
            float w0 = __ldg(wah + h), w1 = __ldg(wah + h + 1);
            p0 += tanhf(C[mt][nt][0] + b0) * w0 + tanhf(C[mt][nt][1] + b1) * w1;
            p1 += tanhf(C[mt][nt][2] + b0) * w0 + tanhf(C[mt][nt][3] + b1) * w1;
        }
        p0 += __shfl_xor_sync(0xffffffffu, p0, 1);
        p0 += __shfl_xor_sync(0xffffffffu, p0, 2);
        p1 += __shfl_xor_sync(0xffffffffu, p1, 1);
        p1 += __shfl_xor_sync(0xffffffffu, p1, 2);
        if (tig == 0) {
            int row = wi * 64 + mt * 16 + g;
            sred[wh * 128 + row]     = p0;
            sred[wh * 128 + row + 8] = p1;
        }
    }
    __syncthreads();
    if (tid < 128) {
        float* outS = sel ? g_so : g_st;   // device-side symbol selection
        outS[m0 + tid] = sred[tid] + sred[128 + tid] + sred[256 + tid] + sred[384 + tid];
    }
}

// ---------------- pass 1: softmax row stats -> g_c ---------------------------
__global__ __launch_bounds__(256) void pass1_kernel(const float* __restrict__ ba) {
    __shared__ float2 sQS[Ll];
    __shared__ float  sB[Ll];
    const int b = blockIdx.y, i0 = blockIdx.x * 128;
    const int tid = threadIdx.x;
    for (int t = tid; t < Ll; t += 256) {
        sQS[t] = g_qs[b * Ll + t];
        sB[t]  = g_base[t];
    }
    __syncthreads();
    const int row = tid >> 1, half = tid & 1;
    const int gi = i0 + row;
    const float sti = g_st[b * Ll + gi] + ba[0];
    const int jb = half * 1024;

    float m = -INFINITY;
    #pragma unroll 4
    for (int t = 0; t < 1024; ++t) {
        int j = jb + t;
        int d = gi - j; d = d < 0 ? -d : d;
        float2 v = sQS[j];
        float x = fmaf(sti, v.x, v.y) * sB[d];
        m = fmaxf(m, x);
    }
    m = fmaxf(m, __shfl_xor_sync(0xffffffffu, m, 1));
    float l = 0.f;
    #pragma unroll 4
    for (int t = 0; t < 1024; ++t) {
        int j = jb + t;
        int d = gi - j; d = d < 0 ? -d : d;
        float2 v = sQS[j];
        float x = fmaf(sti, v.x, v.y) * sB[d];
        l += ex2f(x - m);
    }
    l += __shfl_xor_sync(0xffffffffu, l, 1);
    if (half == 0) g_c[b * Ll + gi] = -(m + lg2f(l));
}

// ---------------- pass 2: bf16-split MMA attention ---------------------------
// block: 128 i-rows x 256 h; j-chunks of 64; V double-buffered via cp.async
constexpr int P2_VHI  = 0;                      // [2][256][72 bf16]
constexpr int P2_VLO  = 2 * 256 * STRB;         // 73728
constexpr int P2_PHI  = 4 * 256 * STRB;         // 147456  [128][72 bf16]
constexpr int P2_PLO  = P2_PHI + 128 * STRB;    // 165888
constexpr int P2_BASE = P2_PLO + 128 * STRB;    // 184320  float[2048]
constexpr int P2_SMEM = P2_BASE + Ll * 4;       // 192512

__global__ __launch_bounds__(256, 1) void pass2_kernel(
    const float* __restrict__ ba, float* __restrict__ out)
{
    extern __shared__ char smc[];
    const int tid = threadIdx.x, wid = tid >> 5, lane = tid & 31;
    const int b = blockIdx.y, i0 = blockIdx.x * 128;
    const int wi = wid >> 2, wh = wid & 3;

    float* sBase = (float*)(smc + P2_BASE);
    for (int t = tid; t < Ll; t += 256) sBase[t] = g_base[t];

    const int prow = tid >> 1, jh = (tid & 1) * 32;
    const int gi = i0 + prow;
    const float sti = g_st[b * Ll + gi] + __ldg(ba);
    const float ci  = g_c [b * Ll + gi];

    const int sub = lane >> 3, lr = lane & 7;
    const uint32_t lrA = (uint32_t)((lr + (sub & 1) * 8) * STRB + (sub >> 1) * 16);
    const uint32_t lrB = (uint32_t)((lr + (sub >> 1) * 8) * STRB + (sub & 1) * 16);

    const __nv_bfloat16* vh_g = g_vhi + (size_t)b * Hh * Ll;
    const __nv_bfloat16* vl_g = g_vlo + (size_t)b * Hh * Ll;

    float C[4][8][4] = {};

    // prologue: async-load V chunk 0 into buffer 0
    {
        #pragma unroll
        for (int k = 0; k < 8; ++k) {
            int idx = tid + k * 256;
            int r = idx >> 3, sg = idx & 7;
            uint32_t d0 = su32(smc + P2_VHI + r * STRB + sg * 16);
            uint32_t d1 = su32(smc + P2_VLO + r * STRB + sg * 16);
            cp16(d0, vh_g + (size_t)r * Ll + sg * 8);
            cp16(d1, vl_g + (size_t)r * Ll + sg * 8);
        }
        asm volatile("cp.async.commit_group;" ::: "memory");
    }
    __syncthreads();   // sBase fully written before any thread's P computation

    for (int t = 0; t < NC; ++t) {
        const int s = t & 1;
        const int j0 = t * JT;
        // prefetch next V chunk into the other buffer
        if (t + 1 < NC) {
            const int j1 = (t + 1) * JT;
            const int nb = s ^ 1;
            #pragma unroll
            for (int k = 0; k < 8; ++k) {
                int idx = tid + k * 256;
                int r = idx >> 3, sg = idx & 7;
                uint32_t d0 = su32(smc + P2_VHI + nb * 36864 + r * STRB + sg * 16);
                uint32_t d1 = su32(smc + P2_VLO + nb * 36864 + r * STRB + sg * 16);
                cp16(d0, vh_g + (size_t)r * Ll + j1 + sg * 8);
                cp16(d1, vl_g + (size_t)r * Ll + j1 + sg * 8);
            }
            asm volatile("cp.async.commit_group;" ::: "memory");
        }
        // compute P tile (normalized weights), bf16 hi/lo split
        {
            #pragma unroll
            for (int u2 = 0; u2 < 16; ++u2) {
                int j = jh + u2 * 2;
                float4 q2 = __ldg((const float4*)(g_qs + b * Ll + j0 + j));
                int d0 = gi - (j0 + j);     d0 = d0 < 0 ? -d0 : d0;
                int d1 = gi - (j0 + j + 1); d1 = d1 < 0 ? -d1 : d1;
                float x0 = fmaf(fmaf(sti, q2.x, q2.y), sBase[d0], ci);
                float x1 = fmaf(fmaf(sti, q2.z, q2.w), sBase[d1], ci);
                float p0 = ex2f(x0), p1 = ex2f(x1);
                uint32_t hp, lp;
                split2(p0, p1, hp, lp);
                *(uint32_t*)(smc + P2_PHI + prow * STRB + j * 2) = hp;
                *(uint32_t*)(smc + P2_PLO + prow * STRB + j * 2) = lp;
            }
        }
        if (t + 1 < NC) asm volatile("cp.async.wait_group 1;" ::: "memory");
        else            asm volatile("cp.async.wait_group 0;" ::: "memory");
        __syncthreads();
        // MMA: C += P * V^T  (3-term bf16 split)
        {
            const uint32_t vhi = su32(smc + P2_VHI + s * 36864);
            const uint32_t vlo = su32(smc + P2_VLO + s * 36864);
            const uint32_t phi = su32(smc + P2_PHI);
            const uint32_t plo = su32(smc + P2_PLO);
            #pragma unroll
            for (int kk = 0; kk < 4; ++kk) {
                const uint32_t kb = kk * 32;
                uint32_t bh[4][4], bl[4][4];
                #pragma unroll
                for (int nt = 0; nt < 4; ++nt) {
                    uint32_t off = (uint32_t)((wh * 64 + nt * 16) * STRB) + kb + lrB;
                    ldm4(bh[nt][0], bh[nt][1], bh[nt][2], bh[nt][3], vhi + off);
                    ldm4(bl[nt][0], bl[nt][1], bl[nt][2], bl[nt][3], vlo + off);
                }
                #pragma unroll
                for (int mt = 0; mt < 4; ++mt) {
                    uint32_t aoff = (uint32_t)((wi * 64 + mt * 16) * STRB) + kb + lrA;
                    uint32_t ah[4], al[4];
                    ldm4(ah[0], ah[1], ah[2], ah[3], phi + aoff);
                    ldm4(al[0], al[1], al[2], al[3], plo + aoff);
                    #pragma unroll
                    for (int nt = 0; nt < 4; ++nt) {
                        mma16816(C[mt][2 * nt],     ah, bh[nt][0], bh[nt][1]);
                        mma16816(C[mt][2 * nt],     al, bh[nt][0], bh[nt][1]);
                        mma16816(C[mt][2 * nt],     ah, bl[nt][0], bl[nt][1]);
                        mma16816(C[mt][2 * nt + 1], ah, bh[nt][2], bh[nt][3]);
                        mma16816(C[mt][2 * nt + 1], al, bh[nt][2], bh[nt][3]);
                        mma16816(C[mt][2 * nt + 1], ah, bl[nt][2], bl[nt][3]);
                    }
                }
            }
        }
        __syncthreads();
    }

    // epilogue: rows already normalized (P used c_i); store directly
    const int g = lane >> 2, tig = lane & 3;
    #pragma unroll
    for (int mt = 0; mt < 4; ++mt) {
        int row = i0 + wi * 64 + mt * 16 + g;
        float* o0 = out + ((size_t)b * Ll + row) * Hh + wh * 64;
        float* o1 = out + ((size_t)b * Ll + row + 8) * Hh + wh * 64;
        #pragma unroll
        for (int nt = 0; nt < 8; ++nt) {
            int h = nt * 8 + tig * 2;
            *(float2*)(o0 + h) = make_float2(C[mt][nt][0], C[mt][nt][1]);
            *(float2*)(o1 + h) = make_float2(C[mt][nt][2], C[mt][nt][3]);
        }
    }
}

// ---------------- launch -----------------------------------------------------
extern "C" void kernel_launch(void* const* d_in, const int* in_sizes, int n_in,
                              void* d_out, int out_size) {
    const float* opinion = (const float*)d_in[0];
    const float* text    = (const float*)d_in[1];
    const int*   pos     = (const int*)d_in[2];
    const float* Wt      = (const float*)d_in[3];
    const float* bt      = (const float*)d_in[4];
    const float* Wo      = (const float*)d_in[5];
    const float* wa      = (const float*)d_in[6];
    const float* ba      = (const float*)d_in[7];
    float* out = (float*)d_out;

    prep0_kernel<<<(Bb * Ll + 255) / 256, 256>>>(pos);
    {
        dim3 g(Ll / 32, Hh / 32, Bb);
        prepv_kernel<<<g, 256>>>(opinion);
    }
    cudaFuncSetAttribute((const void*)s1_mma_kernel,
                         cudaFuncAttributeMaxDynamicSharedMemorySize, S1_SMEM);
    s1_mma_kernel<<<Bb * Ll / 128, 256, S1_SMEM>>>(text,    Wt, bt,      wa,      0);
    s1_mma_kernel<<<Bb * Ll / 128, 256, S1_SMEM>>>(opinion, Wo, nullptr, wa + Hh, 1);
    prep2_kernel<<<(Bb * Ll + 255) / 256, 256>>>();
    {
        dim3 g(Ll / 128, Bb);
        pass1_kernel<<<g, 256>>>(ba);
    }
    cudaFuncSetAttribute((const void*)pass2_kernel,
                         cudaFuncAttributeMaxDynamicSharedMemorySize, P2_SMEM);
    {
        dim3 g(Ll / 128, Bb);
        pass2_kernel<<<g, 256, P2_SMEM>>>(ba, out);
    }
}

// round 5
// speedup vs baseline: 5.9658x; 1.4444x over previous
#include <cuda_runtime.h>
#include <cuda_bf16.h>
#include <cuda_fp16.h>
#include <math.h>
#include <cstdint>

constexpr int Bb = 8, Ll = 2048, Hh = 256;
constexpr int JT = 64, NC = Ll / JT;   // pass2 j-chunks
constexpr int STRB = 144;              // padded smem row stride (bytes)

// ---------------- device scratch (allocation-free) ---------------------------
__device__ float  g_st[Bb * Ll];
__device__ float  g_so[Bb * Ll];
__device__ float  g_q [Bb * Ll];                     // mult_j * log2(e)
__device__ float2 g_qs[Bb * Ll];                     // {q_j, q_j * so_j}
__device__ float  g_c [Bb * Ll];                     // -(m_i + log2 l_i)
__device__ float  g_base[Ll];
__device__ __half g_vh[(size_t)Bb * Hh * Ll];        // V^T [B][H][L] fp16

// ---------------- small helpers ----------------------------------------------
__device__ __forceinline__ uint32_t su32(const void* p) {
    return (uint32_t)__cvta_generic_to_shared(p);
}
__device__ __forceinline__ float ex2f(float x) {
    float r; asm("ex2.approx.f32 %0, %1;" : "=f"(r) : "f"(x)); return r;
}
__device__ __forceinline__ float lg2f(float x) {
    float r; asm("lg2.approx.f32 %0, %1;" : "=f"(r) : "f"(x)); return r;
}
__device__ __forceinline__ void ldm4(uint32_t& r0, uint32_t& r1, uint32_t& r2,
                                     uint32_t& r3, uint32_t a) {
    asm volatile("ldmatrix.sync.aligned.m8n8.x4.shared.b16 {%0,%1,%2,%3}, [%4];"
        : "=r"(r0), "=r"(r1), "=r"(r2), "=r"(r3) : "r"(a));
}
__device__ __forceinline__ void mma16816bf(float* c, const uint32_t* a,
                                           uint32_t b0, uint32_t b1) {
    asm volatile("mma.sync.aligned.m16n8k16.row.col.f32.bf16.bf16.f32 "
        "{%0,%1,%2,%3}, {%4,%5,%6,%7}, {%8,%9}, {%0,%1,%2,%3};"
        : "+f"(c[0]), "+f"(c[1]), "+f"(c[2]), "+f"(c[3])
        : "r"(a[0]), "r"(a[1]), "r"(a[2]), "r"(a[3]), "r"(b0), "r"(b1));
}
__device__ __forceinline__ void mma16816h(float* c, const uint32_t* a,
                                          uint32_t b0, uint32_t b1) {
    asm volatile("mma.sync.aligned.m16n8k16.row.col.f32.f16.f16.f32 "
        "{%0,%1,%2,%3}, {%4,%5,%6,%7}, {%8,%9}, {%0,%1,%2,%3};"
        : "+f"(c[0]), "+f"(c[1]), "+f"(c[2]), "+f"(c[3])
        : "r"(a[0]), "r"(a[1]), "r"(a[2]), "r"(a[3]), "r"(b0), "r"(b1));
}
// split (p0,p1) into packed bf16x2 hi + residual lo (s1 path)
__device__ __forceinline__ void split2(float p0, float p1, uint32_t& hi, uint32_t& lo) {
    asm("cvt.rn.bf16x2.f32 %0, %1, %2;" : "=r"(hi) : "f"(p1), "f"(p0));
    float h0 = __uint_as_float(hi << 16);
    float h1 = __uint_as_float(hi & 0xffff0000u);
    float r0 = p0 - h0, r1 = p1 - h1;
    asm("cvt.rn.bf16x2.f32 %0, %1, %2;" : "=r"(lo) : "f"(r1), "f"(r0));
}
// pack two floats to f16x2 (lo = p0, hi = p1)
__device__ __forceinline__ uint32_t packh2(float p0, float p1) {
    uint32_t r;
    asm("cvt.rn.f16x2.f32 %0, %1, %2;" : "=r"(r) : "f"(p1), "f"(p0));
    return r;
}
__device__ __forceinline__ void cp16(uint32_t dst, const void* src) {
    asm volatile("cp.async.cg.shared.global [%0], [%1], 16;"
        :: "r"(dst), "l"(src) : "memory");
}

// ---------------- prep0: multiplier + base table -----------------------------
__global__ void prep0_kernel(const int* __restrict__ pos) {
    int idx = blockIdx.x * blockDim.x + threadIdx.x;
    if (idx < Bb * Ll) {
        int p = pos[idx];
        bool op = (p >= 19 && p <= 21) || (p >= 33 && p <= 35) || (p >= 41 && p <= 46);
        g_q[idx] = (op ? 8.0f : 1.0f) * 1.44269504088896340736f;
    }
    if (idx < Ll) g_base[idx] = (idx == 0) ? 0.5f : (1.0f / log2f(2.0f + (float)idx));
}

// ---------------- prep2: pack {q, q*so} --------------------------------------
__global__ void prep2_kernel() {
    int idx = blockIdx.x * blockDim.x + threadIdx.x;
    if (idx < Bb * Ll) g_qs[idx] = make_float2(g_q[idx], g_q[idx] * g_so[idx]);
}

// ---------------- prepV: transpose V -> [B][H][L] fp16 -----------------------
__global__ __launch_bounds__(256) void prepv_kernel(const float* __restrict__ V) {
    __shared__ float tile[32][33];
    const int b = blockIdx.z, h0 = blockIdx.y * 32, j0 = blockIdx.x * 32;
    const int tid = threadIdx.x, c = tid & 31, r0 = tid >> 5;
    #pragma unroll
    for (int k = 0; k < 4; ++k) {
        int r = r0 + k * 8;
        tile[r][c] = V[((size_t)b * Ll + j0 + r) * Hh + h0 + c];
    }
    __syncthreads();
    #pragma unroll
    for (int k = 0; k < 4; ++k) {
        int hh = r0 + k * 8;
        float v = tile[c][hh];
        g_vh[((size_t)b * Hh + h0 + hh) * Ll + j0 + c] = __float2half(v);
    }
}

// ---------------- stage 1: bf16-split MMA GEMM + tanh·wa reduction -----------
// block: 128 m-rows x 256 h, 8 warps (2 m-halves x 4 h-quarters), K=256 in 4 chunks
constexpr int S1_XHI = 0;
constexpr int S1_XLO = 128 * STRB;             // 18432
constexpr int S1_WHI = 2 * 128 * STRB;         // 36864
constexpr int S1_WLO = S1_WHI + 256 * STRB;    // 73728
constexpr int S1_RED = S1_WLO + 256 * STRB;    // 110592: float[4][128]
constexpr int S1_SMEM = S1_RED + 4 * 128 * 4;  // 112640

__global__ __launch_bounds__(256, 1) void s1_mma_kernel(
    const float* __restrict__ X, const float* __restrict__ W,
    const float* __restrict__ bias, const float* __restrict__ wah, int sel)
{
    extern __shared__ char smc[];
    const int tid = threadIdx.x, wid = tid >> 5, lane = tid & 31;
    const int m0 = blockIdx.x * 128;
    const int wi = wid >> 2, wh = wid & 3;

    const uint32_t xhi = su32(smc + S1_XHI), xlo = su32(smc + S1_XLO);
    const uint32_t whi = su32(smc + S1_WHI), wlo = su32(smc + S1_WLO);

    const int sub = lane >> 3, lr = lane & 7;
    const uint32_t lrA = (uint32_t)((lr + (sub & 1) * 8) * STRB + (sub >> 1) * 16);
    const uint32_t lrB = (uint32_t)((lr + (sub >> 1) * 8) * STRB + (sub & 1) * 16);

    float C[4][8][4] = {};

    for (int kc = 0; kc < 4; ++kc) {
        __syncthreads();
        #pragma unroll
        for (int q = 0; q < 8; ++q) {
            int idx = tid + q * 256;
            int r = idx >> 4, s2 = idx & 15;
            float4 v = *(const float4*)(X + (size_t)(m0 + r) * Hh + kc * 64 + s2 * 4);
            uint32_t h01, l01, h23, l23;
            split2(v.x, v.y, h01, l01);
            split2(v.z, v.w, h23, l23);
            *(uint2*)(smc + S1_XHI + r * STRB + s2 * 8) = make_uint2(h01, h23);
            *(uint2*)(smc + S1_XLO + r * STRB + s2 * 8) = make_uint2(l01, l23);
        }
        #pragma unroll
        for (int q = 0; q < 16; ++q) {
            int idx = tid + q * 256;
            int r = idx >> 4, s2 = idx & 15;
            float4 v = *(const float4*)(W + (size_t)r * Hh + kc * 64 + s2 * 4);
            uint32_t h01, l01, h23, l23;
            split2(v.x, v.y, h01, l01);
            split2(v.z, v.w, h23, l23);
            *(uint2*)(smc + S1_WHI + r * STRB + s2 * 8) = make_uint2(h01, h23);
            *(uint2*)(smc + S1_WLO + r * STRB + s2 * 8) = make_uint2(l01, l23);
        }
        __syncthreads();
        #pragma unroll
        for (int kk = 0; kk < 4; ++kk) {
            const uint32_t kb = kk * 32;
            uint32_t bh[4][4], bl[4][4];
            #pragma unroll
            for (int nt = 0; nt < 4; ++nt) {
                uint32_t off = (uint32_t)((wh * 64 + nt * 16) * STRB) + kb + lrB;
                ldm4(bh[nt][0], bh[nt][1], bh[nt][2], bh[nt][3], whi + off);
                ldm4(bl[nt][0], bl[nt][1], bl[nt][2], bl[nt][3], wlo + off);
            }
            #pragma unroll
            for (int mt = 0; mt < 4; ++mt) {
                uint32_t aoff = (uint32_t)((wi * 64 + mt * 16) * STRB) + kb + lrA;
                uint32_t ah[4], al[4];
                ldm4(ah[0], ah[1], ah[2], ah[3], xhi + aoff);
                ldm4(al[0], al[1], al[2], al[3], xlo + aoff);
                #pragma unroll
                for (int nt = 0; nt < 4; ++nt) {
                    mma16816bf(C[mt][2 * nt],     ah, bh[nt][0], bh[nt][1]);
                    mma16816bf(C[mt][2 * nt],     al, bh[nt][0], bh[nt][1]);
                    mma16816bf(C[mt][2 * nt],     ah, bl[nt][0], bl[nt][1]);
                    mma16816bf(C[mt][2 * nt + 1], ah, bh[nt][2], bh[nt][3]);
                    mma16816bf(C[mt][2 * nt + 1], al, bh[nt][2], bh[nt][3]);
                    mma16816bf(C[mt][2 * nt + 1], ah, bl[nt][2], bl[nt][3]);
                }
            }
        }
    }

    // epilogue: st[m] = sum_h tanh(C + bias_h) * wa_h
    float* sred = (float*)(smc + S1_RED);
    const int g = lane >> 2, tig = lane & 3;
    __syncthreads();
    #pragma unroll
    for (int mt = 0; mt < 4; ++mt) {
        float p0 = 0.f, p1 = 0.f;
        #pragma unroll
        for (int nt = 0; nt < 8; ++nt) {
            int h = wh * 64 + nt * 8 + tig * 2;
            float b0 = bias ? __ldg(bias + h)     : 0.f;
            float b1 = bias ? __ldg(bias + h + 1) : 0.f;
            float w0 = __ldg(wah + h), w1 = __ldg(wah + h + 1);
            p0 += tanhf(C[mt][nt][0] + b0) * w0 + tanhf(C[mt][nt][1] + b1) * w1;
            p1 += tanhf(C[mt][nt][2] + b0) * w0 + tanhf(C[mt][nt][3] + b1) * w1;
        }
        p0 += __shfl_xor_sync(0xffffffffu, p0, 1);
        p0 += __shfl_xor_sync(0xffffffffu, p0, 2);
        p1 += __shfl_xor_sync(0xffffffffu, p1, 1);
        p1 += __shfl_xor_sync(0xffffffffu, p1, 2);
        if (tig == 0) {
            int row = wi * 64 + mt * 16 + g;
            sred[wh * 128 + row]     = p0;
            sred[wh * 128 + row + 8] = p1;
        }
    }
    __syncthreads();
    if (tid < 128) {
        float* outS = sel ? g_so : g_st;   // device-side symbol selection
        outS[m0 + tid] = sred[tid] + sred[128 + tid] + sred[256 + tid] + sred[384 + tid];
    }
}

// ---------------- pass 1: softmax row stats -> g_c ---------------------------
__global__ __launch_bounds__(256) void pass1_kernel(const float* __restrict__ ba) {
    __shared__ float2 sQS[Ll];
    __shared__ float  sB[Ll];
    const int b = blockIdx.y, i0 = blockIdx.x * 128;
    const int tid = threadIdx.x;
    for (int t = tid; t < Ll; t += 256) {
        sQS[t] = g_qs[b * Ll + t];
        sB[t]  = g_base[t];
    }
    __syncthreads();
    const int row = tid >> 1, half = tid & 1;
    const int gi = i0 + row;
    const float sti = g_st[b * Ll + gi] + ba[0];
    const int jb = half * 1024;

    float m = -INFINITY;
    #pragma unroll 4
    for (int t = 0; t < 1024; ++t) {
        int j = jb + t;
        int d = gi - j; d = d < 0 ? -d : d;
        float2 v = sQS[j];
        float x = fmaf(sti, v.x, v.y) * sB[d];
        m = fmaxf(m, x);
    }
    m = fmaxf(m, __shfl_xor_sync(0xffffffffu, m, 1));
    float l = 0.f;
    #pragma unroll 4
    for (int t = 0; t < 1024; ++t) {
        int j = jb + t;
        int d = gi - j; d = d < 0 ? -d : d;
        float2 v = sQS[j];
        float x = fmaf(sti, v.x, v.y) * sB[d];
        l += ex2f(x - m);
    }
    l += __shfl_xor_sync(0xffffffffu, l, 1);
    if (half == 0) g_c[b * Ll + gi] = -(m + lg2f(l));
}

// ---------------- pass 2: single-fp16 MMA attention --------------------------
// block: 128 i-rows x 256 h; j-chunks of 64; V double-buffered via cp.async
constexpr int P2_V    = 0;                      // [2][256][STRB]  fp16 V^T tiles
constexpr int P2_P    = 2 * 256 * STRB;         // 73728  [128][STRB] fp16 P tile
constexpr int P2_BASE = P2_P + 128 * STRB;      // 92160  float[2048]
constexpr int P2_SMEM = P2_BASE + Ll * 4;       // 100352

__global__ __launch_bounds__(256, 1) void pass2_kernel(
    const float* __restrict__ ba, float* __restrict__ out)
{
    extern __shared__ char smc[];
    const int tid = threadIdx.x, wid = tid >> 5, lane = tid & 31;
    const int b = blockIdx.y, i0 = blockIdx.x * 128;
    const int wi = wid >> 2, wh = wid & 3;

    float* sBase = (float*)(smc + P2_BASE);
    for (int t = tid; t < Ll; t += 256) sBase[t] = g_base[t];

    const int prow = tid >> 1, jh = (tid & 1) * 32;
    const int gi = i0 + prow;
    const float sti = g_st[b * Ll + gi] + __ldg(ba);
    const float ci  = g_c [b * Ll + gi];

    const int sub = lane >> 3, lr = lane & 7;
    const uint32_t lrA = (uint32_t)((lr + (sub & 1) * 8) * STRB + (sub >> 1) * 16);
    const uint32_t lrB = (uint32_t)((lr + (sub >> 1) * 8) * STRB + (sub & 1) * 16);

    const __half* v_g = g_vh + (size_t)b * Hh * Ll;

    float C[4][8][4] = {};

    // prologue: async-load V chunk 0 into buffer 0 (256 rows x 64 fp16 = 32KB)
    {
        #pragma unroll
        for (int k = 0; k < 8; ++k) {
            int idx = tid + k * 256;
            int r = idx >> 3, sg = idx & 7;
            cp16(su32(smc + P2_V + r * STRB + sg * 16), v_g + (size_t)r * Ll + sg * 8);
        }
        asm volatile("cp.async.commit_group;" ::: "memory");
    }
    __syncthreads();   // sBase fully written before any thread's P computation

    for (int t = 0; t < NC; ++t) {
        const int s = t & 1;
        const int j0 = t * JT;
        // prefetch next V chunk into the other buffer
        if (t + 1 < NC) {
            const int j1 = (t + 1) * JT;
            const int nb = s ^ 1;
            #pragma unroll
            for (int k = 0; k < 8; ++k) {
                int idx = tid + k * 256;
                int r = idx >> 3, sg = idx & 7;
                cp16(su32(smc + P2_V + nb * 36864 + r * STRB + sg * 16),
                     v_g + (size_t)r * Ll + j1 + sg * 8);
            }
            asm volatile("cp.async.commit_group;" ::: "memory");
        }
        // compute P tile (normalized weights) in fp16
        {
            #pragma unroll
            for (int u2 = 0; u2 < 16; ++u2) {
                int j = jh + u2 * 2;
                float4 q2 = __ldg((const float4*)(g_qs + b * Ll + j0 + j));
                int d0 = gi - (j0 + j);     d0 = d0 < 0 ? -d0 : d0;
                int d1 = gi - (j0 + j + 1); d1 = d1 < 0 ? -d1 : d1;
                float x0 = fmaf(fmaf(sti, q2.x, q2.y), sBase[d0], ci);
                float x1 = fmaf(fmaf(sti, q2.z, q2.w), sBase[d1], ci);
                *(uint32_t*)(smc + P2_P + prow * STRB + j * 2) =
                    packh2(ex2f(x0), ex2f(x1));
            }
        }
        if (t + 1 < NC) asm volatile("cp.async.wait_group 1;" ::: "memory");
        else            asm volatile("cp.async.wait_group 0;" ::: "memory");
        __syncthreads();
        // MMA: C += P * V^T  (single fp16 term)
        {
            const uint32_t vS = su32(smc + P2_V + s * 36864);
            const uint32_t pS = su32(smc + P2_P);
            #pragma unroll
            for (int kk = 0; kk < 4; ++kk) {
                const uint32_t kb = kk * 32;
                uint32_t bh[4][4];
                #pragma unroll
                for (int nt = 0; nt < 4; ++nt) {
                    uint32_t off = (uint32_t)((wh * 64 + nt * 16) * STRB) + kb + lrB;
                    ldm4(bh[nt][0], bh[nt][1], bh[nt][2], bh[nt][3], vS + off);
                }
                #pragma unroll
                for (int mt = 0; mt < 4; ++mt) {
                    uint32_t aoff = (uint32_t)((wi * 64 + mt * 16) * STRB) + kb + lrA;
                    uint32_t ah[4];
                    ldm4(ah[0], ah[1], ah[2], ah[3], pS + aoff);
                    #pragma unroll
                    for (int nt = 0; nt < 4; ++nt) {
                        mma16816h(C[mt][2 * nt],     ah, bh[nt][0], bh[nt][1]);
                        mma16816h(C[mt][2 * nt + 1], ah, bh[nt][2], bh[nt][3]);
                    }
                }
            }
        }
        __syncthreads();
    }

    // epilogue: rows already normalized (P used c_i); store directly
    const int g = lane >> 2, tig = lane & 3;
    #pragma unroll
    for (int mt = 0; mt < 4; ++mt) {
        int row = i0 + wi * 64 + mt * 16 + g;
        float* o0 = out + ((size_t)b * Ll + row) * Hh + wh * 64;
        float* o1 = out + ((size_t)b * Ll + row + 8) * Hh + wh * 64;
        #pragma unroll
        for (int nt = 0; nt < 8; ++nt) {
            int h = nt * 8 + tig * 2;
            *(float2*)(o0 + h) = make_float2(C[mt][nt][0], C[mt][nt][1]);
            *(float2*)(o1 + h) = make_float2(C[mt][nt][2], C[mt][nt][3]);
        }
    }
}

// ---------------- launch -----------------------------------------------------
extern "C" void kernel_launch(void* const* d_in, const int* in_sizes, int n_in,
                              void* d_out, int out_size) {
    const float* opinion = (const float*)d_in[0];
    const float* text    = (const float*)d_in[1];
    const int*   pos     = (const int*)d_in[2];
    const float* Wt      = (const float*)d_in[3];
    const float* bt      = (const float*)d_in[4];
    const float* Wo      = (const float*)d_in[5];
    const float* wa      = (const float*)d_in[6];
    const float* ba      = (const float*)d_in[7];
    float* out = (float*)d_out;

    prep0_kernel<<<(Bb * Ll + 255) / 256, 256>>>(pos);
    {
        dim3 g(Ll / 32, Hh / 32, Bb);
        prepv_kernel<<<g, 256>>>(opinion);
    }
    cudaFuncSetAttribute((const void*)s1_mma_kernel,
                         cudaFuncAttributeMaxDynamicSharedMemorySize, S1_SMEM);
    s1_mma_kernel<<<Bb * Ll / 128, 256, S1_SMEM>>>(text,    Wt, bt,      wa,      0);
    s1_mma_kernel<<<Bb * Ll / 128, 256, S1_SMEM>>>(opinion, Wo, nullptr, wa + Hh, 1);
    prep2_kernel<<<(Bb * Ll + 255) / 256, 256>>>();
    {
        dim3 g(Ll / 128, Bb);
        pass1_kernel<<<g, 256>>>(ba);
    }
    cudaFuncSetAttribute((const void*)pass2_kernel,
                         cudaFuncAttributeMaxDynamicSharedMemorySize, P2_SMEM);
    {
        dim3 g(Ll / 128, Bb);
        pass2_kernel<<<g, 256, P2_SMEM>>>(ba, out);
    }
}